// round 15
// baseline (speedup 1.0000x reference)
#include <cuda_runtime.h>
#include <cstdint>

// Who2com reduces exactly to: out = bevs (softmax over axis 1 followed by
// sum over axis 1 is identically 1.0; everything upstream only feeds the
// softmax logits). Kernel = 84 MB copy.
//
// Plateau at 27.136 us (three identical readings). All axes swept and closed
// except block SHAPE (every prior round used 256 thr/block):
//  - plain LDG.128 loads (anything else regresses)
//  - STG.256 + L2::evict_last (writeback deferral; the only measured win)
//  - exact-division geometry
// This round: 512 threads x 2560 blocks x 2 vec8/thread (= 2,621,440 exact).
// Halves waves (8.65 vs 17.3), 4 warps/SMSP, bigger per-CTA LDG batch into
// the L1tex queue. Everything else R7-identical.

__global__ __launch_bounds__(512) void who2com_copy_kernel(
    const float4* __restrict__ src, float* __restrict__ dst)
{
    const int nthreads = gridDim.x * blockDim.x;          // 1,310,720
    const int tid = blockIdx.x * blockDim.x + threadIdx.x;

    #pragma unroll
    for (int k = 0; k < 2; k++) {
        const int c = tid + k * nthreads;                 // vec8 index
        // Plain 128-bit loads: the proven fastest read path.
        float4 a = src[2 * c + 0];
        float4 b = src[2 * c + 1];
        // 256-bit store with L2::evict_last: writebacks deferred past the
        // kernel's critical path.
        asm volatile(
            "st.global.L2::evict_last.v8.f32 [%0], "
            "{%1, %2, %3, %4, %5, %6, %7, %8};"
            :: "l"(dst + (size_t)c * 8),
               "f"(a.x), "f"(a.y), "f"(a.z), "f"(a.w),
               "f"(b.x), "f"(b.y), "f"(b.z), "f"(b.w)
            : "memory");
    }
}

extern "C" void kernel_launch(void* const* d_in, const int* in_sizes, int n_in,
                              void* d_out, int out_size)
{
    const float4* src = (const float4*)d_in[0];   // bevs: [1,4,80,256,256] fp32
    float* dst = (float*)d_out;

    // out_size = 20,971,520 floats = 2,621,440 vec8 = 1,310,720 threads * 2.
    const int threads = 512;
    const int blocks = 2560;
    who2com_copy_kernel<<<blocks, threads>>>(src, dst);
}